// round 16
// baseline (speedup 1.0000x reference)
#include <cuda_runtime.h>
#include <cuda_bf16.h>
#include <math.h>
#include <stdint.h>

// Problem constants
#define NB 16
#define TT 12
#define NN 325
#define D_DIM 128
#define F_DIM 256
#define H_HEADS 8
#define HD 16
#define R_TOTAL (NB*TT*NN)   // 62400
#define M_TILES ((R_TOTAL + 127) / 128)   // 488 (qkv)
#define M2_TILES (R_TOTAL / 64)           // 975 (block2, exact)

// Attention padding
#define NKP 336
#define VT_STRIDE 344

// log2(e)/4 folded into q so attention uses plain exp2
#define QSCALE 0.36067376022224085f

// ---------------------------------------------------------------------------
// Scratch (device globals: allocation-guard safe)
// ---------------------------------------------------------------------------
__device__ __nv_bfloat16 g_qb [R_TOTAL * D_DIM];   // pre-scaled by QSCALE
__device__ __nv_bfloat16 g_kb [R_TOTAL * D_DIM];
__device__ __nv_bfloat16 g_vb [R_TOTAL * D_DIM];
__device__ __nv_bfloat16 g_attb[R_TOTAL * D_DIM];
__device__ __nv_bfloat16 g_Wqb[D_DIM * D_DIM];
__device__ __nv_bfloat16 g_Wkb[D_DIM * D_DIM];
__device__ __nv_bfloat16 g_Wvb[D_DIM * D_DIM];
__device__ __nv_bfloat16 g_Wob[D_DIM * D_DIM];
__device__ __nv_bfloat16 g_W1b[D_DIM * F_DIM];
__device__ __nv_bfloat16 g_W2b[F_DIM * D_DIM];

// ---------------------------------------------------------------------------
// Common helpers
// ---------------------------------------------------------------------------
__device__ __forceinline__ uint32_t packbf(float x, float y) {  // lo=x, hi=y
    uint32_t r;
    asm("cvt.rn.bf16x2.f32 %0, %1, %2;" : "=r"(r) : "f"(y), "f"(x));
    return r;
}

__device__ __forceinline__ float ex2(float x) {
    float r;
    asm("ex2.approx.f32 %0, %1;" : "=f"(r) : "f"(x));
    return r;
}

__device__ __forceinline__ void mma_bf16(float c[4], const uint32_t a[4], const uint32_t b[2]) {
    asm volatile(
        "mma.sync.aligned.m16n8k16.row.col.f32.bf16.bf16.f32 "
        "{%0,%1,%2,%3}, {%4,%5,%6,%7}, {%8,%9}, {%0,%1,%2,%3};"
        : "+f"(c[0]), "+f"(c[1]), "+f"(c[2]), "+f"(c[3])
        : "r"(a[0]), "r"(a[1]), "r"(a[2]), "r"(a[3]), "r"(b[0]), "r"(b[1]));
}

__device__ __forceinline__ void ldsm_x4(uint32_t r[4], uint32_t addr) {
    asm volatile("ldmatrix.sync.aligned.m8n8.x4.shared.b16 {%0,%1,%2,%3}, [%4];"
        : "=r"(r[0]), "=r"(r[1]), "=r"(r[2]), "=r"(r[3]) : "r"(addr));
}
__device__ __forceinline__ void ldsm_x2(uint32_t r[2], uint32_t addr) {
    asm volatile("ldmatrix.sync.aligned.m8n8.x2.shared.b16 {%0,%1}, [%2];"
        : "=r"(r[0]), "=r"(r[1]) : "r"(addr));
}
__device__ __forceinline__ void ldsm_x2t(uint32_t r[2], uint32_t addr) {
    asm volatile("ldmatrix.sync.aligned.m8n8.x2.trans.shared.b16 {%0,%1}, [%2];"
        : "=r"(r[0]), "=r"(r[1]) : "r"(addr));
}

__device__ __forceinline__ void cp16(uint32_t smaddr, const void* gaddr) {
    asm volatile("cp.async.cg.shared.global [%0], [%1], 16;" :: "r"(smaddr), "l"(gaddr));
}
__device__ __forceinline__ void cp_commit() {
    asm volatile("cp.async.commit_group;");
}
template <int N>
__device__ __forceinline__ void cp_wait() {
    asm volatile("cp.async.wait_group %0;" :: "n"(N));
}

// ---------------------------------------------------------------------------
// Geometry
// ---------------------------------------------------------------------------
#define BS_U32 68
#define B_SLOT (32 * BS_U32 * 4)            // 8704
#define ATILE_STRIDE 272
#define ATILE_BYTES (128 * ATILE_STRIDE)    // 34816 (qkv, 128 rows)
#define MID_STRIDE 528
#define CS_STRIDE 132

#define QKV_SMEM  (ATILE_BYTES + 4 * B_SLOT)    // 69632 -> 2 CTA/SM

// block2 (64-row tiles), regions:
#define B2_R0 0                               // C0 -> h_fp32 (64*132*4 = 33792)
#define B2_R1 33792                           // attbA -> h_bf16 (64*272 = 17408)
#define B2_R2 51200                           // 2 W slots (17408)
#define B2_R3 68608                           // mid (64*528 = 33792) -> C2
#define B2_SMEM 102400                        // 2 CTA/SM

// ---------------------------------------------------------------------------
// Fills
// ---------------------------------------------------------------------------
__device__ __forceinline__ void fill_A_from_f32_128(char* sm,
                                                    const float* __restrict__ A,
                                                    int lda, int row0) {
    const int tid = threadIdx.x;
    #pragma unroll
    for (int it = 0; it < 16; it++) {
        int idx = tid + it * 256;
        int r = idx >> 5, c4 = (idx & 31) << 2;
        int row = row0 + r;
        if (row > R_TOTAL - 1) row = R_TOTAL - 1;
        float4 v = *(const float4*)(A + (size_t)row * lda + c4);
        uint32_t* p = (uint32_t*)(sm + r * ATILE_STRIDE + c4 * 2);
        p[0] = packbf(v.x, v.y);
        p[1] = packbf(v.z, v.w);
    }
}

// 64-row bf16 A tile via cp.async (no commit). Rows exact (no clamp needed).
__device__ __forceinline__ void fill_A64_bf16(uint32_t aTile,
                                              const __nv_bfloat16* __restrict__ A,
                                              int row0) {
    const int tid = threadIdx.x;
    #pragma unroll
    for (int it = 0; it < 4; it++) {
        int idx = tid + it * 256;
        int r = idx >> 4, seg = idx & 15;
        cp16(aTile + r * ATILE_STRIDE + seg * 16,
             A + (size_t)(row0 + r) * D_DIM + seg * 8);
    }
}

// One 32-k B chunk (no commit)
__device__ __forceinline__ void fill_Bchunk(uint32_t dst,
                                            const __nv_bfloat16* __restrict__ B, int ldb,
                                            int bcol0, int kofs) {
    const int tid = threadIdx.x;
    #pragma unroll
    for (int it = 0; it < 2; it++) {
        int idx = tid + it * 256;
        int k = idx >> 4, seg = idx & 15;
        cp16(dst + k * (BS_U32 * 4) + seg * 16,
             B + (size_t)(kofs + k) * ldb + bcol0 + seg * 8);
    }
}

// ---------------------------------------------------------------------------
// MMA chunks
// ---------------------------------------------------------------------------
// 128-row CTA tile (qkv): warp 64x32, acc[4][4][4]
__device__ __forceinline__ void mma_chunk128(uint32_t aTile, uint32_t bSlot, int ch,
                                             float acc[4][4][4], int wm, int wn, int lane) {
    const uint32_t aBase = aTile + (uint32_t)(wm * 64 + (lane & 15)) * ATILE_STRIDE
                         + (uint32_t)(ch * 64) + ((uint32_t)(lane >> 4) << 4);
    const uint32_t bBase = bSlot + (uint32_t)(lane & 15) * (BS_U32 * 4) + (uint32_t)wn * 64;
    #pragma unroll
    for (int ks = 0; ks < 2; ks++) {
        uint32_t af[4][4], bfr[4][2];
        #pragma unroll
        for (int mt = 0; mt < 4; mt++)
            ldsm_x4(af[mt], aBase + mt * (16 * ATILE_STRIDE) + ks * 32);
        #pragma unroll
        for (int nt = 0; nt < 4; nt++)
            ldsm_x2t(bfr[nt], bBase + ks * (16 * BS_U32 * 4) + nt * 16);
        #pragma unroll
        for (int mt = 0; mt < 4; mt++)
            #pragma unroll
            for (int nt = 0; nt < 4; nt++)
                mma_bf16(acc[mt][nt], af[mt], bfr[nt]);
    }
}

// 64-row CTA tile (block2): warp 32x32, acc[2][4][4]
__device__ __forceinline__ void mma_chunk64(uint32_t aTile, uint32_t aStride,
                                            uint32_t bSlot, int ch,
                                            float acc[2][4][4], int wm, int wn, int lane) {
    const uint32_t aBase = aTile + (uint32_t)(wm * 32 + (lane & 15)) * aStride
                         + (uint32_t)(ch * 64) + ((uint32_t)(lane >> 4) << 4);
    const uint32_t bBase = bSlot + (uint32_t)(lane & 15) * (BS_U32 * 4) + (uint32_t)wn * 64;
    #pragma unroll
    for (int ks = 0; ks < 2; ks++) {
        uint32_t af[2][4], bfr[4][2];
        #pragma unroll
        for (int mt = 0; mt < 2; mt++)
            ldsm_x4(af[mt], aBase + mt * (16 * aStride) + ks * 32);
        #pragma unroll
        for (int nt = 0; nt < 4; nt++)
            ldsm_x2t(bfr[nt], bBase + ks * (16 * BS_U32 * 4) + nt * 16);
        #pragma unroll
        for (int mt = 0; mt < 2; mt++)
            #pragma unroll
            for (int nt = 0; nt < 4; nt++)
                mma_bf16(acc[mt][nt], af[mt], bfr[nt]);
    }
}

__device__ __forceinline__ void zero_acc64(float acc[2][4][4]) {
    #pragma unroll
    for (int i = 0; i < 2; i++)
        #pragma unroll
        for (int j = 0; j < 4; j++)
            #pragma unroll
            for (int r = 0; r < 4; r++) acc[i][j][r] = 0.f;
}

// Stage 64-row accumulators to smem C[64][132]; includes trailing sync.
__device__ __forceinline__ void stage_c64(float* smf, float acc[2][4][4],
                                          int wm, int wn, int lane) {
    const int gid = lane >> 2;
    const int tig = lane & 3;
    #pragma unroll
    for (int mt = 0; mt < 2; mt++) {
        #pragma unroll
        for (int nt = 0; nt < 4; nt++) {
            int row = wm * 32 + mt * 16 + gid;
            int col = wn * 32 + nt * 8 + (tig << 1);
            *(float2*)(smf + row * CS_STRIDE + col)       = make_float2(acc[mt][nt][0], acc[mt][nt][1]);
            *(float2*)(smf + (row + 8) * CS_STRIDE + col) = make_float2(acc[mt][nt][2], acc[mt][nt][3]);
        }
    }
    __syncthreads();
}

// ---------------------------------------------------------------------------
// Weight conversion (fp32 -> bf16)
// ---------------------------------------------------------------------------
__global__ void k_cvt_w(const float* __restrict__ Wq, const float* __restrict__ Wk,
                        const float* __restrict__ Wv, const float* __restrict__ Wo,
                        const float* __restrict__ W1, const float* __restrict__ W2) {
    const int n4 = (4 * 16384 + 2 * 32768) / 4;   // 32768
    for (int i = blockIdx.x * blockDim.x + threadIdx.x; i < n4; i += gridDim.x * blockDim.x) {
        const float* src;
        __nv_bfloat16* dst;
        int off;
        if      (i < 4096)  { src = Wq; dst = g_Wqb; off = i; }
        else if (i < 8192)  { src = Wk; dst = g_Wkb; off = i - 4096; }
        else if (i < 12288) { src = Wv; dst = g_Wvb; off = i - 8192; }
        else if (i < 16384) { src = Wo; dst = g_Wob; off = i - 12288; }
        else if (i < 24576) { src = W1; dst = g_W1b; off = i - 16384; }
        else                { src = W2; dst = g_W2b; off = i - 24576; }
        float4 v = *(const float4*)(src + (size_t)off * 4);
        uint32_t* d = (uint32_t*)dst + off * 2;
        d[0] = packbf(v.x, v.y);
        d[1] = packbf(v.z, v.w);
    }
}

// ---------------------------------------------------------------------------
// Kernel 1: QKV — grid (488, 3), one weight per CTA, 2 CTA/SM. (proven)
// ---------------------------------------------------------------------------
__global__ void __launch_bounds__(256, 2) k_qkv(const float* __restrict__ x,
                                                const float* __restrict__ bq,
                                                const float* __restrict__ bk,
                                                const float* __restrict__ bv) {
    extern __shared__ char sm[];
    const uint32_t smB = (uint32_t)__cvta_generic_to_shared(sm);
    const uint32_t aTile = smB;
    const uint32_t bBase = smB + ATILE_BYTES;
    const int row0 = blockIdx.x << 7;
    const int which = blockIdx.y;

    const __nv_bfloat16* W = (which == 0) ? g_Wqb : (which == 1) ? g_Wkb : g_Wvb;
    const float* bias      = (which == 0) ? bq : (which == 1) ? bk : bv;
    __nv_bfloat16* out     = (which == 0) ? g_qb : (which == 1) ? g_kb : g_vb;
    const float scale      = (which == 0) ? QSCALE : 1.f;

    const int tid  = threadIdx.x;
    const int warp = tid >> 5;
    const int lane = tid & 31;
    const int gid  = lane >> 2;
    const int tig  = lane & 3;
    const int wm   = warp >> 2;
    const int wn   = warp & 3;

    #pragma unroll
    for (int s = 0; s < 4; s++)
        fill_Bchunk(bBase + s * B_SLOT, W, D_DIM, 0, s << 5);
    cp_commit();
    fill_A_from_f32_128(sm, x, D_DIM, row0);
    cp_wait<0>();
    __syncthreads();

    float acc[4][4][4];
    #pragma unroll
    for (int i = 0; i < 4; i++)
        #pragma unroll
        for (int j = 0; j < 4; j++)
            #pragma unroll
            for (int r = 0; r < 4; r++) acc[i][j][r] = 0.f;
    #pragma unroll
    for (int ch = 0; ch < 4; ch++)
        mma_chunk128(aTile, bBase + ch * B_SLOT, ch, acc, wm, wn, lane);

    #pragma unroll
    for (int mt = 0; mt < 4; mt++) {
        int r0 = row0 + wm * 64 + mt * 16 + gid;
        int r1 = r0 + 8;
        #pragma unroll
        for (int nt = 0; nt < 4; nt++) {
            int col = wn * 32 + nt * 8 + (tig << 1);
            float b0 = bias[col], b1 = bias[col + 1];
            if (r0 < R_TOTAL)
                *(uint32_t*)(out + (size_t)r0 * D_DIM + col) =
                    packbf((acc[mt][nt][0] + b0) * scale, (acc[mt][nt][1] + b1) * scale);
            if (r1 < R_TOTAL)
                *(uint32_t*)(out + (size_t)r1 * D_DIM + col) =
                    packbf((acc[mt][nt][2] + b0) * scale, (acc[mt][nt][3] + b1) * scale);
        }
    }
}

// ---------------------------------------------------------------------------
// Kernel 2: attention per (b,h,t). grid = 1536, block = 256. (proven R8 form)
// ---------------------------------------------------------------------------
__global__ void __launch_bounds__(256) attn_kernel() {
    __shared__ __align__(16) uint32_t Qs[NKP * 8];
    __shared__ __align__(16) uint32_t Ks[NKP * 12];
    __shared__ __align__(16) uint32_t Vt[24 * (VT_STRIDE / 2)];

    const int bid = blockIdx.x;
    const int t = bid % TT;
    const int h = (bid / TT) % H_HEADS;
    const int b = bid / (TT * H_HEADS);
    const int row0 = (b * TT + t) * NN;
    const int hoff = h * HD;
    const int tid = threadIdx.x;

    __nv_bfloat16* Vtb = (__nv_bfloat16*)Vt;

    for (int idx = tid; idx < NKP * 2; idx += 256) {
        int m = idx >> 1;
        int seg = idx & 1;
        uint4 qv, kv, vv;
        if (m < NN) {
            size_t base = (size_t)(row0 + m) * D_DIM + hoff + seg * 8;
            qv = *(const uint4*)(g_qb + base);
            kv = *(const uint4*)(g_kb + base);
            vv = *(const uint4*)(g_vb + base);
        } else {
            qv = kv = vv = make_uint4(0, 0, 0, 0);
        }
        *(uint4*)(Qs + m * 8 + seg * 4) = qv;
        *(uint4*)(Ks + m * 12 + seg * 4) = kv;
        int d0 = seg * 8;
        uint32_t vu[4] = {vv.x, vv.y, vv.z, vv.w};
        #pragma unroll
        for (int j = 0; j < 4; j++) {
            __nv_bfloat162 p = *(__nv_bfloat162*)&vu[j];
            Vtb[(d0 + 2 * j)     * VT_STRIDE + m] = p.x;
            Vtb[(d0 + 2 * j + 1) * VT_STRIDE + m] = p.y;
        }
    }
    for (int i = tid; i < 8 * (VT_STRIDE / 2); i += 256) {
        int r = 16 + i / (VT_STRIDE / 2);
        int cu = i % (VT_STRIDE / 2);
        int m = cu * 2;
        uint32_t val = 0;
        if (r == 16) {
            if (m + 1 < NN)      val = 0x3F803F80u;
            else if (m < NN)     val = 0x00003F80u;
        }
        Vt[r * (VT_STRIDE / 2) + cu] = val;
    }
    __syncthreads();

    const int warp = tid >> 5;
    const int lane = tid & 31;
    const int gid  = lane >> 2;
    const int tig  = lane & 3;

    const int rowInTile = (lane & 7) + ((lane >> 4) << 3);
    const uint32_t off16 = (uint32_t)(lane & 8) << 1;
    const uint32_t ksSm = (uint32_t)__cvta_generic_to_shared(Ks);
    const uint32_t vtSm = (uint32_t)__cvta_generic_to_shared(Vt);
    const uint32_t kLane  = ksSm + (uint32_t)rowInTile * 48 + off16;
    const uint32_t vLane  = vtSm + (uint32_t)rowInTile * (VT_STRIDE * 2) + off16;
    const uint32_t v1Lane = vtSm + (uint32_t)(16 + (lane & 7)) * (VT_STRIDE * 2) + off16;

    for (int mt = warp; mt < 21; mt += 8) {
        const int m0 = mt << 4;
        uint32_t qa[4];
        qa[0] = Qs[(m0 + gid) * 8 + tig];
        qa[1] = Qs[(m0 + gid + 8) * 8 + tig];
        qa[2] = Qs[(m0 + gid) * 8 + tig + 4];
        qa[3] = Qs[(m0 + gid + 8) * 8 + tig + 4];

        float oc0[4] = {0.f, 0.f, 0.f, 0.f};
        float oc1[4] = {0.f, 0.f, 0.f, 0.f};
        float oc2[4] = {0.f, 0.f, 0.f, 0.f};

        for (int j = 0; j < 21; j++) {
            float c0[4] = {0.f, 0.f, 0.f, 0.f};
            float c1[4] = {0.f, 0.f, 0.f, 0.f};
            uint32_t kr[4];
            ldsm_x4(kr, kLane + (uint32_t)j * (16 * 48));
            mma_bf16(c0, qa, kr);
            mma_bf16(c1, qa, kr + 2);

            float p00 = ex2(c0[0]);
            float p01 = ex2(c0[1]);
            float p02 = ex2(c0[2]);
            float p03 = ex2(c0[3]);
            float p10 = ex2(c1[0]);
            float p11 = ex2(c1[1]);
            float p12 = ex2(c1[2]);
            float p13 = ex2(c1[3]);

            uint32_t pa[4];
            pa[0] = packbf(p00, p01);
            pa[1] = packbf(p02, p03);
            pa[2] = packbf(p10, p11);
            pa[3] = packbf(p12, p13);

            uint32_t vr[4], v1r[2];
            ldsm_x4(vr, vLane + (uint32_t)j * 32);
            ldsm_x2(v1r, v1Lane + (uint32_t)j * 32);
            mma_bf16(oc0, pa, vr);
            mma_bf16(oc1, pa, vr + 2);
            mma_bf16(oc2, pa, v1r);
        }

        float rs0 = __shfl_sync(0xffffffffu, oc2[0], lane & ~3);
        float rs1 = __shfl_sync(0xffffffffu, oc2[2], lane & ~3);
        float i0 = 1.f / rs0;
        float i1 = 1.f / rs1;

        int r0 = m0 + gid;
        int r1 = m0 + gid + 8;
        if (r0 < NN) {
            __nv_bfloat16* op = g_attb + (size_t)(row0 + r0) * D_DIM + hoff;
            *(uint32_t*)(op + 2 * tig)     = packbf(oc0[0] * i0, oc0[1] * i0);
            *(uint32_t*)(op + 8 + 2 * tig) = packbf(oc1[0] * i0, oc1[1] * i0);
        }
        if (r1 < NN) {
            __nv_bfloat16* op = g_attb + (size_t)(row0 + r1) * D_DIM + hoff;
            *(uint32_t*)(op + 2 * tig)     = packbf(oc0[2] * i1, oc0[3] * i1);
            *(uint32_t*)(op + 8 + 2 * tig) = packbf(oc1[2] * i1, oc1[3] * i1);
        }
    }
}

// ---------------------------------------------------------------------------
// Kernel 3 (FUSED, 64-row tiles, 2 CTA/SM): out = LN2(h + gelu(h@W1+b1)@W2 + b2),
// h = LN1(x + attb@Wo + bo). Unified 20-chunk double-buffered weight stream.
// ---------------------------------------------------------------------------
__global__ void __launch_bounds__(256, 2) k_block2(const float* __restrict__ x,
                                                   const float* __restrict__ bo,
                                                   const float* __restrict__ g1,
                                                   const float* __restrict__ b1ln,
                                                   const float* __restrict__ b1,
                                                   const float* __restrict__ b2,
                                                   const float* __restrict__ g2,
                                                   const float* __restrict__ bt2,
                                                   float* __restrict__ out) {
    extern __shared__ char sm[];
    const uint32_t smB = (uint32_t)__cvta_generic_to_shared(sm);
    const int row0 = blockIdx.x << 6;      // 64-row tile, exact coverage

    const int tid  = threadIdx.x;
    const int warp = tid >> 5;
    const int lane = tid & 31;
    const int gid  = lane >> 2;
    const int tig  = lane & 3;
    const int wm   = warp >> 2;            // 0..1 -> 32-row slab
    const int wn   = warp & 3;             // 0..3 -> 32-col slab
    const int lrow = tid >> 2;             // 0..63 (LN: 4 threads/row)
    const int qt   = tid & 3;              // quarter index (32 cols)

    float* hF  = (float*)(sm + B2_R0);     // C0 -> h fp32, stride 132
    float* c2F = (float*)(sm + B2_R3);     // GEMM2 C, stride 132
    __nv_bfloat16* midb = (__nv_bfloat16*)(sm + B2_R3);

    const uint32_t slot0 = smB + B2_R2;
    const uint32_t slot1 = smB + B2_R2 + B_SLOT;

    // chunk index -> weight source
    auto issue_chunk = [&](int i) {
        uint32_t dst = (i & 1) ? slot1 : slot0;
        if (i < 4)       fill_Bchunk(dst, g_Wob, D_DIM, 0,   (i)      << 5);
        else if (i < 8)  fill_Bchunk(dst, g_W1b, F_DIM, 0,   (i - 4)  << 5);
        else if (i < 12) fill_Bchunk(dst, g_W1b, F_DIM, 128, (i - 8)  << 5);
        else             fill_Bchunk(dst, g_W2b, D_DIM, 0,   (i - 12) << 5);
        cp_commit();
    };

    // Prologue: A (attb) + chunk0 as group0; chunk1 as group1.
    fill_A64_bf16(smB + B2_R1, g_attb, row0);
    fill_Bchunk(slot0, g_Wob, D_DIM, 0, 0);
    cp_commit();
    fill_Bchunk(slot1, g_Wob, D_DIM, 0, 32);
    cp_commit();

    float acc[2][4][4];
    zero_acc64(acc);

    #pragma unroll 1
    for (int i = 0; i < 20; i++) {
        if (i == 19) cp_wait<0>(); else cp_wait<1>();
        __syncthreads();

        // A selection
        uint32_t aT; uint32_t aStr; int ch;
        if (i < 12) { aT = smB + B2_R1; aStr = ATILE_STRIDE; ch = i & 3; }
        else        { aT = smB + B2_R3; aStr = MID_STRIDE;   ch = i - 12; }
        mma_chunk64(aT, aStr, (i & 1) ? slot1 : slot0, ch, acc, wm, wn, lane);
        __syncthreads();                  // slot (i&1) free for refill

        if (i + 2 < 20) issue_chunk(i + 2);

        if (i == 3) {
            // GEMM0 done: C0 -> R0, LN1 -> h fp32 (R0 in place) + h bf16 (R1)
            stage_c64(hF, acc, wm, wn, lane);
            {
                int row = row0 + lrow;
                float* Cr = hF + lrow * CS_STRIDE + qt * 32;
                const float* xr = x + (size_t)row * D_DIM + qt * 32;
                const float* br = bo + qt * 32;
                float s1 = 0.f, s2 = 0.f;
                #pragma unroll
                for (int c = 0; c < 32; c += 4) {
                    float4 cv = *(const float4*)(Cr + c);
                    float4 rv = *(const float4*)(xr + c);
                    float4 bv = *(const float4*)(br + c);
                    float v0 = cv.x + bv.x + rv.x;
                    float v1 = cv.y + bv.y + rv.y;
                    float v2 = cv.z + bv.z + rv.z;
                    float v3 = cv.w + bv.w + rv.w;
                    s1 += (v0 + v1) + (v2 + v3);
                    s2 += (v0 * v0 + v1 * v1) + (v2 * v2 + v3 * v3);
                }
                s1 += __shfl_xor_sync(0xffffffffu, s1, 1);
                s2 += __shfl_xor_sync(0xffffffffu, s2, 1);
                s1 += __shfl_xor_sync(0xffffffffu, s1, 2);
                s2 += __shfl_xor_sync(0xffffffffu, s2, 2);
                float mean = s1 * (1.f / 128.f);
                float var  = s2 * (1.f / 128.f) - mean * mean;
                float rstd = rsqrtf(var + 1e-5f);
                const float* gr = g1 + qt * 32;
                const float* btr = b1ln + qt * 32;
                uint32_t* hb = (uint32_t*)(sm + B2_R1 + lrow * ATILE_STRIDE + qt * 64);
                #pragma unroll
                for (int c = 0; c < 32; c += 4) {
                    float4 cv = *(const float4*)(Cr + c);
                    float4 rv = *(const float4*)(xr + c);
                    float4 bv = *(const float4*)(br + c);
                    float4 gv = *(const float4*)(gr + c);
                    float4 bb = *(const float4*)(btr + c);
                    float4 o;
                    o.x = (cv.x + bv.x + rv.x - mean) * rstd * gv.x + bb.x;
                    o.y = (cv.y + bv.y + rv.y - mean) * rstd * gv.y + bb.y;
                    o.z = (cv.z + bv.z + rv.z - mean) * rstd * gv.z + bb.z;
                    o.w = (cv.w + bv.w + rv.w - mean) * rstd * gv.w + bb.w;
                    *(float4*)(Cr + c) = o;
                    hb[c >> 1]       = packbf(o.x, o.y);
                    hb[(c >> 1) + 1] = packbf(o.z, o.w);
                }
            }
            zero_acc64(acc);
        } else if (i == 7 || i == 11) {
            // GEMM1 half done: gelu + bias -> mid (R3)
            const int col0 = (i == 7) ? 0 : 128;
            #pragma unroll
            for (int mt = 0; mt < 2; mt++) {
                int lr0 = wm * 32 + mt * 16 + gid;
                int lr1 = lr0 + 8;
                #pragma unroll
                for (int nt = 0; nt < 4; nt++) {
                    int col = col0 + wn * 32 + nt * 8 + (tig << 1);
                    float bb0 = b1[col], bb1 = b1[col + 1];
                    float v0 = acc[mt][nt][0] + bb0;
                    float v1 = acc[mt][nt][1] + bb1;
                    float v2 = acc[mt][nt][2] + bb0;
                    float v3 = acc[mt][nt][3] + bb1;
                    float e0 = 0.5f * v0 * (1.f + erff(v0 * 0.70710678118654752f));
                    float e1 = 0.5f * v1 * (1.f + erff(v1 * 0.70710678118654752f));
                    float e2 = 0.5f * v2 * (1.f + erff(v2 * 0.70710678118654752f));
                    float e3 = 0.5f * v3 * (1.f + erff(v3 * 0.70710678118654752f));
                    *(uint32_t*)((char*)midb + lr0 * MID_STRIDE + col * 2) = packbf(e0, e1);
                    *(uint32_t*)((char*)midb + lr1 * MID_STRIDE + col * 2) = packbf(e2, e3);
                }
            }
            zero_acc64(acc);
        }
    }

    __syncthreads();            // mid reads done before C2 overlays R3
    stage_c64(c2F, acc, wm, wn, lane);

    // LN2 -> out
    {
        int row = row0 + lrow;
        const float* Cr = c2F + lrow * CS_STRIDE + qt * 32;
        const float* hr = hF + lrow * CS_STRIDE + qt * 32;
        const float* br = b2 + qt * 32;
        float s1 = 0.f, s2 = 0.f;
        #pragma unroll
        for (int c = 0; c < 32; c += 4) {
            float4 cv = *(const float4*)(Cr + c);
            float4 rv = *(const float4*)(hr + c);
            float4 bv = *(const float4*)(br + c);
            float v0 = cv.x + bv.x + rv.x;
            float v1 = cv.y + bv.y + rv.y;
            float v2 = cv.z + bv.z + rv.z;
            float v3 = cv.w + bv.w + rv.w;
            s1 += (v0 + v1) + (v2 + v3);
            s2 += (v0 * v0 + v1 * v1) + (v2 * v2 + v3 * v3);
        }
        s1 += __shfl_xor_sync(0xffffffffu, s1, 1);
        s2 += __shfl_xor_sync(0xffffffffu, s2, 1);
        s1 += __shfl_xor_sync(0xffffffffu, s1, 2);
        s2 += __shfl_xor_sync(0xffffffffu, s2, 2);
        float mean = s1 * (1.f / 128.f);
        float var  = s2 * (1.f / 128.f) - mean * mean;
        float rstd = rsqrtf(var + 1e-5f);
        float* orow = out + (size_t)row * D_DIM + qt * 32;
        const float* gr = g2 + qt * 32;
        const float* btr = bt2 + qt * 32;
        #pragma unroll
        for (int c = 0; c < 32; c += 4) {
            float4 cv = *(const float4*)(Cr + c);
            float4 rv = *(const float4*)(hr + c);
            float4 bv = *(const float4*)(br + c);
            float4 gv = *(const float4*)(gr + c);
            float4 bb = *(const float4*)(btr + c);
            float4 o;
            o.x = (cv.x + bv.x + rv.x - mean) * rstd * gv.x + bb.x;
            o.y = (cv.y + bv.y + rv.y - mean) * rstd * gv.y + bb.y;
            o.z = (cv.z + bv.z + rv.z - mean) * rstd * gv.z + bb.z;
            o.w = (cv.w + bv.w + rv.w - mean) * rstd * gv.w + bb.w;
            *(float4*)(orow + c) = o;
        }
    }
}

// ---------------------------------------------------------------------------
extern "C" void kernel_launch(void* const* d_in, const int* in_sizes, int n_in,
                              void* d_out, int out_size) {
    const float* x     = (const float*)d_in[0];
    const float* Wq    = (const float*)d_in[1];
    const float* bq    = (const float*)d_in[2];
    const float* Wk    = (const float*)d_in[3];
    const float* bk    = (const float*)d_in[4];
    const float* Wv    = (const float*)d_in[5];
    const float* bv    = (const float*)d_in[6];
    const float* Wo    = (const float*)d_in[7];
    const float* bo    = (const float*)d_in[8];
    const float* ln1_g = (const float*)d_in[9];
    const float* ln1_b = (const float*)d_in[10];
    const float* W1    = (const float*)d_in[11];
    const float* b1    = (const float*)d_in[12];
    const float* W2    = (const float*)d_in[13];
    const float* b2    = (const float*)d_in[14];
    const float* ln2_g = (const float*)d_in[15];
    const float* ln2_b = (const float*)d_in[16];
    float* out = (float*)d_out;

    cudaFuncSetAttribute(k_qkv,    cudaFuncAttributeMaxDynamicSharedMemorySize, QKV_SMEM);
    cudaFuncSetAttribute(k_block2, cudaFuncAttributeMaxDynamicSharedMemorySize, B2_SMEM);

    k_cvt_w<<<64, 512>>>(Wq, Wk, Wv, Wo, W1, W2);
    k_qkv<<<dim3(M_TILES, 3), 256, QKV_SMEM>>>(x, bq, bk, bv);
    attn_kernel<<<NB * H_HEADS * TT, 256>>>();
    k_block2<<<M2_TILES, 256, B2_SMEM>>>(x, bo, ln1_g, ln1_b, b1, b2, ln2_g, ln2_b, out);
}

// round 17
// speedup vs baseline: 1.0311x; 1.0311x over previous
#include <cuda_runtime.h>
#include <cuda_bf16.h>
#include <math.h>
#include <stdint.h>

// Problem constants
#define NB 16
#define TT 12
#define NN 325
#define D_DIM 128
#define F_DIM 256
#define H_HEADS 8
#define HD 16
#define R_TOTAL (NB*TT*NN)   // 62400
#define M_TILES ((R_TOTAL + 127) / 128)   // 488

// Attention padding
#define NKP 336
#define VS_U32 20            // V row stride: 20 u32 = 80B (conflict-free ldsm)

// log2(e)/4 folded into q so attention uses plain exp2
#define QSCALE 0.36067376022224085f

// ---------------------------------------------------------------------------
// Scratch (device globals: allocation-guard safe)
// ---------------------------------------------------------------------------
__device__ __nv_bfloat16 g_qb [R_TOTAL * D_DIM];   // pre-scaled by QSCALE
__device__ __nv_bfloat16 g_kb [R_TOTAL * D_DIM];
__device__ __nv_bfloat16 g_vb [R_TOTAL * D_DIM];
__device__ __nv_bfloat16 g_attb[R_TOTAL * D_DIM];
__device__ __nv_bfloat16 g_Wqb[D_DIM * D_DIM];
__device__ __nv_bfloat16 g_Wkb[D_DIM * D_DIM];
__device__ __nv_bfloat16 g_Wvb[D_DIM * D_DIM];
__device__ __nv_bfloat16 g_Wob[D_DIM * D_DIM];
__device__ __nv_bfloat16 g_W1b[D_DIM * F_DIM];
__device__ __nv_bfloat16 g_W2b[F_DIM * D_DIM];

// ---------------------------------------------------------------------------
// Common helpers
// ---------------------------------------------------------------------------
__device__ __forceinline__ uint32_t packbf(float x, float y) {  // lo=x, hi=y
    uint32_t r;
    asm("cvt.rn.bf16x2.f32 %0, %1, %2;" : "=r"(r) : "f"(y), "f"(x));
    return r;
}

__device__ __forceinline__ float ex2(float x) {
    float r;
    asm("ex2.approx.f32 %0, %1;" : "=f"(r) : "f"(x));
    return r;
}

__device__ __forceinline__ void mma_bf16(float c[4], const uint32_t a[4], const uint32_t b[2]) {
    asm volatile(
        "mma.sync.aligned.m16n8k16.row.col.f32.bf16.bf16.f32 "
        "{%0,%1,%2,%3}, {%4,%5,%6,%7}, {%8,%9}, {%0,%1,%2,%3};"
        : "+f"(c[0]), "+f"(c[1]), "+f"(c[2]), "+f"(c[3])
        : "r"(a[0]), "r"(a[1]), "r"(a[2]), "r"(a[3]), "r"(b[0]), "r"(b[1]));
}

__device__ __forceinline__ void ldsm_x4(uint32_t r[4], uint32_t addr) {
    asm volatile("ldmatrix.sync.aligned.m8n8.x4.shared.b16 {%0,%1,%2,%3}, [%4];"
        : "=r"(r[0]), "=r"(r[1]), "=r"(r[2]), "=r"(r[3]) : "r"(addr));
}
__device__ __forceinline__ void ldsm_x2t(uint32_t r[2], uint32_t addr) {
    asm volatile("ldmatrix.sync.aligned.m8n8.x2.trans.shared.b16 {%0,%1}, [%2];"
        : "=r"(r[0]), "=r"(r[1]) : "r"(addr));
}

__device__ __forceinline__ void cp16(uint32_t smaddr, const void* gaddr) {
    asm volatile("cp.async.cg.shared.global [%0], [%1], 16;" :: "r"(smaddr), "l"(gaddr));
}
__device__ __forceinline__ void cp_commit() {
    asm volatile("cp.async.commit_group;");
}
template <int N>
__device__ __forceinline__ void cp_wait() {
    asm volatile("cp.async.wait_group %0;" :: "n"(N));
}

// ---------------------------------------------------------------------------
// GEMM geometry: CTA 128x128 out tile, 8 warps (2x4), warp 64x32.
// ---------------------------------------------------------------------------
#define BS_U32 68
#define B_SLOT (32 * BS_U32 * 4)            // 8704
#define ATILE_STRIDE 272
#define ATILE_BYTES (128 * ATILE_STRIDE)    // 34816
#define MID_STRIDE 528
#define MID_BYTES (128 * MID_STRIDE)        // 67584
#define CS_STRIDE 132

#define QKV_SMEM  (ATILE_BYTES + 4 * B_SLOT)    // 69632 -> 2 CTA/SM

// Fused block2 smem regions (R15 layout)
#define FB_R0 0                              // attbA+Wo -> C -> h_fp32 (69632)
#define FB_R1 69632                          // h_bf16 A-tile (34816)
#define FB_R2 104448                         // 4 streaming W slots (34816)
#define FB_R3 139264                         // mid bf16 -> C2 (67584)
#define FB_SMEM 206848

// Fill bf16 A tile by converting fp32 source rows.
__device__ __forceinline__ void fill_A_from_f32(char* sm, uint32_t aTileOff,
                                                const float* __restrict__ A,
                                                int lda, int row0) {
    const int tid = threadIdx.x;
    #pragma unroll
    for (int it = 0; it < 16; it++) {
        int idx = tid + it * 256;
        int r = idx >> 5, c4 = (idx & 31) << 2;
        int row = row0 + r;
        if (row > R_TOTAL - 1) row = R_TOTAL - 1;
        float4 v = *(const float4*)(A + (size_t)row * lda + c4);
        uint32_t* p = (uint32_t*)(sm + aTileOff + r * ATILE_STRIDE + c4 * 2);
        p[0] = packbf(v.x, v.y);
        p[1] = packbf(v.z, v.w);
    }
}

// Fill bf16 A tile from bf16 source via cp.async (no commit).
__device__ __forceinline__ void fill_A_bf16(uint32_t aTile,
                                            const __nv_bfloat16* __restrict__ A,
                                            int lda, int row0) {
    const int tid = threadIdx.x;
    #pragma unroll
    for (int it = 0; it < 8; it++) {
        int idx = tid + it * 256;
        int r = idx >> 4, seg = idx & 15;
        int row = row0 + r;
        if (row > R_TOTAL - 1) row = R_TOTAL - 1;
        cp16(aTile + r * ATILE_STRIDE + seg * 16,
             A + (size_t)row * lda + seg * 8);
    }
}

// Fill one 32-k B chunk (no commit)
__device__ __forceinline__ void fill_Bchunk(uint32_t dst,
                                            const __nv_bfloat16* __restrict__ B, int ldb,
                                            int bcol0, int kofs) {
    const int tid = threadIdx.x;
    #pragma unroll
    for (int it = 0; it < 2; it++) {
        int idx = tid + it * 256;
        int k = idx >> 4, seg = idx & 15;
        cp16(dst + k * (BS_U32 * 4) + seg * 16,
             B + (size_t)(kofs + k) * ldb + bcol0 + seg * 8);
    }
}

// One 32-k chunk of MMAs; ch selects the 64-byte column slice of A rows.
__device__ __forceinline__ void mma_chunk(uint32_t aTile, uint32_t aStride,
                                          uint32_t bSlot, int ch,
                                          float acc[4][4][4], int wm, int wn, int lane) {
    const uint32_t aBase = aTile + (uint32_t)(wm * 64 + (lane & 15)) * aStride
                         + (uint32_t)(ch * 64) + ((uint32_t)(lane >> 4) << 4);
    const uint32_t bBase = bSlot + (uint32_t)(lane & 15) * (BS_U32 * 4) + (uint32_t)wn * 64;
    #pragma unroll
    for (int ks = 0; ks < 2; ks++) {
        uint32_t af[4][4], bfr[4][2];
        #pragma unroll
        for (int mt = 0; mt < 4; mt++)
            ldsm_x4(af[mt], aBase + mt * (16 * aStride) + ks * 32);
        #pragma unroll
        for (int nt = 0; nt < 4; nt++)
            ldsm_x2t(bfr[nt], bBase + ks * (16 * BS_U32 * 4) + nt * 16);
        #pragma unroll
        for (int mt = 0; mt < 4; mt++)
            #pragma unroll
            for (int nt = 0; nt < 4; nt++)
                mma_bf16(acc[mt][nt], af[mt], bfr[nt]);
    }
}

__device__ __forceinline__ void zero_acc(float acc[4][4][4]) {
    #pragma unroll
    for (int i = 0; i < 4; i++)
        #pragma unroll
        for (int j = 0; j < 4; j++)
            #pragma unroll
            for (int r = 0; r < 4; r++) acc[i][j][r] = 0.f;
}

// Stage accumulators to smem C[128][132] at smf; includes trailing sync.
__device__ __forceinline__ void stage_c(float* smf, float acc[4][4][4]) {
    const int tid  = threadIdx.x;
    const int warp = tid >> 5;
    const int lane = tid & 31;
    const int gid  = lane >> 2;
    const int tig  = lane & 3;
    const int wm   = warp >> 2;
    const int wn   = warp & 3;
    #pragma unroll
    for (int mt = 0; mt < 4; mt++) {
        #pragma unroll
        for (int nt = 0; nt < 4; nt++) {
            int row = wm * 64 + mt * 16 + gid;
            int col = wn * 32 + nt * 8 + (tig << 1);
            *(float2*)(smf + row * CS_STRIDE + col)       = make_float2(acc[mt][nt][0], acc[mt][nt][1]);
            *(float2*)(smf + (row + 8) * CS_STRIDE + col) = make_float2(acc[mt][nt][2], acc[mt][nt][3]);
        }
    }
    __syncthreads();
}

// ---------------------------------------------------------------------------
// Weight conversion (fp32 -> bf16)
// ---------------------------------------------------------------------------
__global__ void k_cvt_w(const float* __restrict__ Wq, const float* __restrict__ Wk,
                        const float* __restrict__ Wv, const float* __restrict__ Wo,
                        const float* __restrict__ W1, const float* __restrict__ W2) {
    const int n4 = (4 * 16384 + 2 * 32768) / 4;   // 32768
    for (int i = blockIdx.x * blockDim.x + threadIdx.x; i < n4; i += gridDim.x * blockDim.x) {
        const float* src;
        __nv_bfloat16* dst;
        int off;
        if      (i < 4096)  { src = Wq; dst = g_Wqb; off = i; }
        else if (i < 8192)  { src = Wk; dst = g_Wkb; off = i - 4096; }
        else if (i < 12288) { src = Wv; dst = g_Wvb; off = i - 8192; }
        else if (i < 16384) { src = Wo; dst = g_Wob; off = i - 12288; }
        else if (i < 24576) { src = W1; dst = g_W1b; off = i - 16384; }
        else                { src = W2; dst = g_W2b; off = i - 24576; }
        float4 v = *(const float4*)(src + (size_t)off * 4);
        uint32_t* d = (uint32_t*)dst + off * 2;
        d[0] = packbf(v.x, v.y);
        d[1] = packbf(v.z, v.w);
    }
}

// ---------------------------------------------------------------------------
// Kernel 1: QKV — grid (488, 3), one weight per CTA, 2 CTA/SM. (proven)
// ---------------------------------------------------------------------------
__global__ void __launch_bounds__(256, 2) k_qkv(const float* __restrict__ x,
                                                const float* __restrict__ bq,
                                                const float* __restrict__ bk,
                                                const float* __restrict__ bv) {
    extern __shared__ char sm[];
    const uint32_t smB = (uint32_t)__cvta_generic_to_shared(sm);
    const uint32_t aTile = smB;
    const uint32_t bBase = smB + ATILE_BYTES;
    const int row0 = blockIdx.x << 7;
    const int which = blockIdx.y;

    const __nv_bfloat16* W = (which == 0) ? g_Wqb : (which == 1) ? g_Wkb : g_Wvb;
    const float* bias      = (which == 0) ? bq : (which == 1) ? bk : bv;
    __nv_bfloat16* out     = (which == 0) ? g_qb : (which == 1) ? g_kb : g_vb;
    const float scale      = (which == 0) ? QSCALE : 1.f;

    const int tid  = threadIdx.x;
    const int warp = tid >> 5;
    const int lane = tid & 31;
    const int gid  = lane >> 2;
    const int tig  = lane & 3;
    const int wm   = warp >> 2;
    const int wn   = warp & 3;

    #pragma unroll
    for (int s = 0; s < 4; s++)
        fill_Bchunk(bBase + s * B_SLOT, W, D_DIM, 0, s << 5);
    cp_commit();
    fill_A_from_f32(sm, 0, x, D_DIM, row0);
    cp_wait<0>();
    __syncthreads();

    float acc[4][4][4];
    zero_acc(acc);
    #pragma unroll
    for (int ch = 0; ch < 4; ch++)
        mma_chunk(aTile, ATILE_STRIDE, bBase + ch * B_SLOT, ch, acc, wm, wn, lane);

    #pragma unroll
    for (int mt = 0; mt < 4; mt++) {
        int r0 = row0 + wm * 64 + mt * 16 + gid;
        int r1 = r0 + 8;
        #pragma unroll
        for (int nt = 0; nt < 4; nt++) {
            int col = wn * 32 + nt * 8 + (tig << 1);
            float b0 = bias[col], b1 = bias[col + 1];
            if (r0 < R_TOTAL)
                *(uint32_t*)(out + (size_t)r0 * D_DIM + col) =
                    packbf((acc[mt][nt][0] + b0) * scale, (acc[mt][nt][1] + b1) * scale);
            if (r1 < R_TOTAL)
                *(uint32_t*)(out + (size_t)r1 * D_DIM + col) =
                    packbf((acc[mt][nt][2] + b0) * scale, (acc[mt][nt][3] + b1) * scale);
        }
    }
}

// ---------------------------------------------------------------------------
// Kernel 2: attention per (b,h,t). grid = 1536, block = 256.
// V stored ROW-MAJOR [m][16] (80B stride, conflict-free) with ones col at 16;
// V fragments via ldsm_x2t (same path as GEMM B tiles). No transpose fill.
// ---------------------------------------------------------------------------
__global__ void __launch_bounds__(256) attn_kernel() {
    __shared__ __align__(16) uint32_t Qs[NKP * 8];       // [336][16] bf16, 32B rows
    __shared__ __align__(16) uint32_t Ks[NKP * 12];      // 48B rows (ldsm-clean)
    __shared__ __align__(16) uint32_t Vs[NKP * VS_U32];  // 80B rows: 16 V + ones@16 + pad

    const int bid = blockIdx.x;
    const int t = bid % TT;
    const int h = (bid / TT) % H_HEADS;
    const int b = bid / (TT * H_HEADS);
    const int row0 = (b * TT + t) * NN;
    const int hoff = h * HD;
    const int tid = threadIdx.x;

    // Fill Q/K/V (all row-major, vector stores)
    for (int idx = tid; idx < NKP * 2; idx += 256) {
        int m = idx >> 1;
        int seg = idx & 1;
        uint4 qv, kv, vv;
        if (m < NN) {
            size_t base = (size_t)(row0 + m) * D_DIM + hoff + seg * 8;
            qv = *(const uint4*)(g_qb + base);
            kv = *(const uint4*)(g_kb + base);
            vv = *(const uint4*)(g_vb + base);
        } else {
            qv = kv = vv = make_uint4(0, 0, 0, 0);
        }
        *(uint4*)(Qs + m * 8 + seg * 4) = qv;
        *(uint4*)(Ks + m * 12 + seg * 4) = kv;
        *(uint4*)(Vs + m * VS_U32 + seg * 4) = vv;
    }
    // Ones col (16) + zero pad cols 17-23 (u32 indices 8..11)
    for (int m = tid; m < NKP; m += 256) {
        Vs[m * VS_U32 + 8]  = (m < NN) ? 0x00003F80u : 0u;
        Vs[m * VS_U32 + 9]  = 0u;
        Vs[m * VS_U32 + 10] = 0u;
        Vs[m * VS_U32 + 11] = 0u;
    }
    __syncthreads();

    const int warp = tid >> 5;
    const int lane = tid & 31;
    const int gid  = lane >> 2;
    const int tig  = lane & 3;

    const int rowInTile = (lane & 7) + ((lane >> 4) << 3);
    const uint32_t off16 = (uint32_t)(lane & 8) << 1;
    const uint32_t ksSm = (uint32_t)__cvta_generic_to_shared(Ks);
    const uint32_t vsSm = (uint32_t)__cvta_generic_to_shared(Vs);
    const uint32_t kLane = ksSm + (uint32_t)rowInTile * 48 + off16;
    const uint32_t vLane = vsSm + (uint32_t)(lane & 15) * (VS_U32 * 4);

    for (int mt = warp; mt < 21; mt += 8) {
        const int m0 = mt << 4;
        uint32_t qa[4];
        qa[0] = Qs[(m0 + gid) * 8 + tig];
        qa[1] = Qs[(m0 + gid + 8) * 8 + tig];
        qa[2] = Qs[(m0 + gid) * 8 + tig + 4];
        qa[3] = Qs[(m0 + gid + 8) * 8 + tig + 4];

        float oc0[4] = {0.f, 0.f, 0.f, 0.f};
        float oc1[4] = {0.f, 0.f, 0.f, 0.f};
        float oc2[4] = {0.f, 0.f, 0.f, 0.f};

        for (int j = 0; j < 21; j++) {
            float c0[4] = {0.f, 0.f, 0.f, 0.f};
            float c1[4] = {0.f, 0.f, 0.f, 0.f};
            uint32_t kr[4];
            ldsm_x4(kr, kLane + (uint32_t)j * (16 * 48));
            mma_bf16(c0, qa, kr);
            mma_bf16(c1, qa, kr + 2);

            float p00 = ex2(c0[0]);
            float p01 = ex2(c0[1]);
            float p02 = ex2(c0[2]);
            float p03 = ex2(c0[3]);
            float p10 = ex2(c1[0]);
            float p11 = ex2(c1[1]);
            float p12 = ex2(c1[2]);
            float p13 = ex2(c1[3]);

            uint32_t pa[4];
            pa[0] = packbf(p00, p01);
            pa[1] = packbf(p02, p03);
            pa[2] = packbf(p10, p11);
            pa[3] = packbf(p12, p13);

            const uint32_t vj = vLane + (uint32_t)j * (16 * VS_U32 * 4);
            uint32_t vb0[2], vb1[2], v1r[2];
            ldsm_x2t(vb0, vj);         // V cols 0-7
            ldsm_x2t(vb1, vj + 16);    // V cols 8-15
            ldsm_x2t(v1r, vj + 32);    // ones col 16 (+zero 17-23)
            mma_bf16(oc0, pa, vb0);
            mma_bf16(oc1, pa, vb1);
            mma_bf16(oc2, pa, v1r);
        }

        float rs0 = __shfl_sync(0xffffffffu, oc2[0], lane & ~3);
        float rs1 = __shfl_sync(0xffffffffu, oc2[2], lane & ~3);
        float i0 = 1.f / rs0;
        float i1 = 1.f / rs1;

        int r0 = m0 + gid;
        int r1 = m0 + gid + 8;
        if (r0 < NN) {
            __nv_bfloat16* op = g_attb + (size_t)(row0 + r0) * D_DIM + hoff;
            *(uint32_t*)(op + 2 * tig)     = packbf(oc0[0] * i0, oc0[1] * i0);
            *(uint32_t*)(op + 8 + 2 * tig) = packbf(oc1[0] * i0, oc1[1] * i0);
        }
        if (r1 < NN) {
            __nv_bfloat16* op = g_attb + (size_t)(row0 + r1) * D_DIM + hoff;
            *(uint32_t*)(op + 2 * tig)     = packbf(oc0[2] * i1, oc0[3] * i1);
            *(uint32_t*)(op + 8 + 2 * tig) = packbf(oc1[2] * i1, oc1[3] * i1);
        }
    }
}

// ---------------------------------------------------------------------------
// Kernel 3 (FULLY FUSED, R15 proven): out = LN2(h + gelu(h@W1+b1)@W2 + b2),
// h = LN1(x + attb@Wo + bo). h never touches DRAM. 1 CTA/SM, smem 206848.
// ---------------------------------------------------------------------------
__global__ void __launch_bounds__(256) k_block2(const float* __restrict__ x,
                                                const float* __restrict__ bo,
                                                const float* __restrict__ g1,
                                                const float* __restrict__ b1ln,
                                                const float* __restrict__ b1,
                                                const float* __restrict__ b2,
                                                const float* __restrict__ g2,
                                                const float* __restrict__ bt2,
                                                float* __restrict__ out) {
    extern __shared__ char sm[];
    const uint32_t smB = (uint32_t)__cvta_generic_to_shared(sm);
    const int row0 = blockIdx.x << 7;

    const int tid  = threadIdx.x;
    const int warp = tid >> 5;
    const int lane = tid & 31;
    const int gid  = lane >> 2;
    const int tig  = lane & 3;
    const int wm   = warp >> 2;
    const int wn   = warp & 3;
    const int lrow = tid >> 1;
    const int half = tid & 1;

    float* hF   = (float*)(sm + FB_R0);
    float* c2F  = (float*)(sm + FB_R3);

    fill_A_bf16(smB + FB_R0, g_attb, D_DIM, row0);
    #pragma unroll
    for (int s = 0; s < 4; s++)
        fill_Bchunk(smB + FB_R0 + ATILE_BYTES + s * B_SLOT, g_Wob, D_DIM, 0, s << 5);
    cp_commit();
    #pragma unroll
    for (int s = 0; s < 4; s++)
        fill_Bchunk(smB + FB_R2 + s * B_SLOT, g_W1b, F_DIM, 0, s << 5);
    cp_commit();
    cp_wait<1>();
    __syncthreads();

    float acc[4][4][4];
    zero_acc(acc);
    #pragma unroll
    for (int ch = 0; ch < 4; ch++)
        mma_chunk(smB + FB_R0, ATILE_STRIDE, smB + FB_R0 + ATILE_BYTES + ch * B_SLOT,
                  ch, acc, wm, wn, lane);

    __syncthreads();
    stage_c(hF, acc);

    // LN1: h fp32 in place (R0), h bf16 -> R1
    {
        int row = row0 + lrow;
        if (row < R_TOTAL) {
            float* Cr = hF + lrow * CS_STRIDE + half * 64;
            const float* xr = x + (size_t)row * D_DIM + half * 64;
            const float* br = bo + half * 64;
            float s1 = 0.f, s2 = 0.f;
            #pragma unroll
            for (int c = 0; c < 64; c += 4) {
                float4 cv = *(const float4*)(Cr + c);
                float4 rv = *(const float4*)(xr + c);
                float4 bv = *(const float4*)(br + c);
                float v0 = cv.x + bv.x + rv.x;
                float v1 = cv.y + bv.y + rv.y;
                float v2 = cv.z + bv.z + rv.z;
                float v3 = cv.w + bv.w + rv.w;
                s1 += (v0 + v1) + (v2 + v3);
                s2 += (v0 * v0 + v1 * v1) + (v2 * v2 + v3 * v3);
            }
            s1 += __shfl_xor_sync(0xffffffffu, s1, 1);
            s2 += __shfl_xor_sync(0xffffffffu, s2, 1);
            float mean = s1 * (1.f / 128.f);
            float var  = s2 * (1.f / 128.f) - mean * mean;
            float rstd = rsqrtf(var + 1e-5f);
            const float* gr = g1 + half * 64;
            const float* btr = b1ln + half * 64;
            uint32_t* hb = (uint32_t*)(sm + FB_R1 + lrow * ATILE_STRIDE + half * 128);
            #pragma unroll
            for (int c = 0; c < 64; c += 4) {
                float4 cv = *(const float4*)(Cr + c);
                float4 rv = *(const float4*)(xr + c);
                float4 bv = *(const float4*)(br + c);
                float4 gv = *(const float4*)(gr + c);
                float4 bb = *(const float4*)(btr + c);
                float4 o;
                o.x = (cv.x + bv.x + rv.x - mean) * rstd * gv.x + bb.x;
                o.y = (cv.y + bv.y + rv.y - mean) * rstd * gv.y + bb.y;
                o.z = (cv.z + bv.z + rv.z - mean) * rstd * gv.z + bb.z;
                o.w = (cv.w + bv.w + rv.w - mean) * rstd * gv.w + bb.w;
                *(float4*)(Cr + c) = o;
                hb[c >> 1]       = packbf(o.x, o.y);
                hb[(c >> 1) + 1] = packbf(o.z, o.w);
            }
        } else {
            float s1 = 0.f, s2 = 0.f;
            s1 += __shfl_xor_sync(0xffffffffu, s1, 1);
            s2 += __shfl_xor_sync(0xffffffffu, s2, 1);
            (void)s1; (void)s2;
        }
    }
    cp_wait<0>();
    __syncthreads();

    __nv_bfloat16* midb = (__nv_bfloat16*)(sm + FB_R3);

    // GEMM1 half 0
    zero_acc(acc);
    #pragma unroll
    for (int ch = 0; ch < 4; ch++)
        mma_chunk(smB + FB_R1, ATILE_STRIDE, smB + FB_R2 + ch * B_SLOT, ch, acc, wm, wn, lane);

    #pragma unroll
    for (int mt = 0; mt < 4; mt++) {
        int lr0 = wm * 64 + mt * 16 + gid;
        int lr1 = lr0 + 8;
        #pragma unroll
        for (int nt = 0; nt < 4; nt++) {
            int col = wn * 32 + nt * 8 + (tig << 1);
            float bb0 = b1[col], bb1 = b1[col + 1];
            float v0 = acc[mt][nt][0] + bb0;
            float v1 = acc[mt][nt][1] + bb1;
            float v2 = acc[mt][nt][2] + bb0;
            float v3 = acc[mt][nt][3] + bb1;
            float e0 = 0.5f * v0 * (1.f + erff(v0 * 0.70710678118654752f));
            float e1 = 0.5f * v1 * (1.f + erff(v1 * 0.70710678118654752f));
            float e2 = 0.5f * v2 * (1.f + erff(v2 * 0.70710678118654752f));
            float e3 = 0.5f * v3 * (1.f + erff(v3 * 0.70710678118654752f));
            *(uint32_t*)((char*)midb + lr0 * MID_STRIDE + col * 2) = packbf(e0, e1);
            *(uint32_t*)((char*)midb + lr1 * MID_STRIDE + col * 2) = packbf(e2, e3);
        }
    }
    __syncthreads();

    // GEMM1 half 1
    #pragma unroll
    for (int s = 0; s < 4; s++)
        fill_Bchunk(smB + FB_R2 + s * B_SLOT, g_W1b, F_DIM, 128, s << 5);
    cp_commit();
    cp_wait<0>();
    __syncthreads();

    zero_acc(acc);
    #pragma unroll
    for (int ch = 0; ch < 4; ch++)
        mma_chunk(smB + FB_R1, ATILE_STRIDE, smB + FB_R2 + ch * B_SLOT, ch, acc, wm, wn, lane);

    #pragma unroll
    for (int mt = 0; mt < 4; mt++) {
        int lr0 = wm * 64 + mt * 16 + gid;
        int lr1 = lr0 + 8;
        #pragma unroll
        for (int nt = 0; nt < 4; nt++) {
            int col = 128 + wn * 32 + nt * 8 + (tig << 1);
            float bb0 = b1[col], bb1 = b1[col + 1];
            float v0 = acc[mt][nt][0] + bb0;
            float v1 = acc[mt][nt][1] + bb1;
            float v2 = acc[mt][nt][2] + bb0;
            float v3 = acc[mt][nt][3] + bb1;
            float e0 = 0.5f * v0 * (1.f + erff(v0 * 0.70710678118654752f));
            float e1 = 0.5f * v1 * (1.f + erff(v1 * 0.70710678118654752f));
            float e2 = 0.5f * v2 * (1.f + erff(v2 * 0.70710678118654752f));
            float e3 = 0.5f * v3 * (1.f + erff(v3 * 0.70710678118654752f));
            *(uint32_t*)((char*)midb + lr0 * MID_STRIDE + col * 2) = packbf(e0, e1);
            *(uint32_t*)((char*)midb + lr1 * MID_STRIDE + col * 2) = packbf(e2, e3);
        }
    }
    __syncthreads();

    // GEMM2: mid @ W2 (k=256, two batches of 4 chunks through R2)
    zero_acc(acc);
    #pragma unroll
    for (int batch = 0; batch < 2; batch++) {
        #pragma unroll
        for (int s = 0; s < 4; s++)
            fill_Bchunk(smB + FB_R2 + s * B_SLOT, g_W2b, D_DIM, 0, (batch * 4 + s) << 5);
        cp_commit();
        cp_wait<0>();
        __syncthreads();
        #pragma unroll
        for (int s = 0; s < 4; s++)
            mma_chunk(smB + FB_R3, MID_STRIDE, smB + FB_R2 + s * B_SLOT,
                      batch * 4 + s, acc, wm, wn, lane);
        __syncthreads();
    }

    stage_c(c2F, acc);

    // LN2 -> out
    {
        int row = row0 + lrow;
        if (row < R_TOTAL) {
            const float* Cr = c2F + lrow * CS_STRIDE + half * 64;
            const float* hr = hF + lrow * CS_STRIDE + half * 64;
            const float* br = b2 + half * 64;
            float s1 = 0.f, s2 = 0.f;
            #pragma unroll
            for (int c = 0; c < 64; c += 4) {
                float4 cv = *(const float4*)(Cr + c);
                float4 rv = *(const float4*)(hr + c);
                float4 bv = *(const float4*)(br + c);
                float v0 = cv.x + bv.x + rv.x;
                float v1 = cv.y + bv.y + rv.y;
                float v2 = cv.z + bv.z + rv.z;
                float v3 = cv.w + bv.w + rv.w;
                s1 += (v0 + v1) + (v2 + v3);
                s2 += (v0 * v0 + v1 * v1) + (v2 * v2 + v3 * v3);
            }
            s1 += __shfl_xor_sync(0xffffffffu, s1, 1);
            s2 += __shfl_xor_sync(0xffffffffu, s2, 1);
            float mean = s1 * (1.f / 128.f);
            float var  = s2 * (1.f / 128.f) - mean * mean;
            float rstd = rsqrtf(var + 1e-5f);
            float* orow = out + (size_t)row * D_DIM + half * 64;
            const float* gr = g2 + half * 64;
            const float* btr = bt2 + half * 64;
            #pragma unroll
            for (int c = 0; c < 64; c += 4) {
                float4 cv = *(const float4*)(Cr + c);
                float4 rv = *(const float4*)(hr + c);
                float4 bv = *(const float4*)(br + c);
                float4 gv = *(const float4*)(gr + c);
                float4 bb = *(const float4*)(btr + c);
                float4 o;
                o.x = (cv.x + bv.x + rv.x - mean) * rstd * gv.x + bb.x;
                o.y = (cv.y + bv.y + rv.y - mean) * rstd * gv.y + bb.y;
                o.z = (cv.z + bv.z + rv.z - mean) * rstd * gv.z + bb.z;
                o.w = (cv.w + bv.w + rv.w - mean) * rstd * gv.w + bb.w;
                *(float4*)(orow + c) = o;
            }
        } else {
            float s1 = 0.f, s2 = 0.f;
            s1 += __shfl_xor_sync(0xffffffffu, s1, 1);
            s2 += __shfl_xor_sync(0xffffffffu, s2, 1);
            (void)s1; (void)s2;
        }
    }
}

// ---------------------------------------------------------------------------
extern "C" void kernel_launch(void* const* d_in, const int* in_sizes, int n_in,
                              void* d_out, int out_size) {
    const float* x     = (const float*)d_in[0];
    const float* Wq    = (const float*)d_in[1];
    const float* bq    = (const float*)d_in[2];
    const float* Wk    = (const float*)d_in[3];
    const float* bk    = (const float*)d_in[4];
    const float* Wv    = (const float*)d_in[5];
    const float* bv    = (const float*)d_in[6];
    const float* Wo    = (const float*)d_in[7];
    const float* bo    = (const float*)d_in[8];
    const float* ln1_g = (const float*)d_in[9];
    const float* ln1_b = (const float*)d_in[10];
    const float* W1    = (const float*)d_in[11];
    const float* b1    = (const float*)d_in[12];
    const float* W2    = (const float*)d_in[13];
    const float* b2    = (const float*)d_in[14];
    const float* ln2_g = (const float*)d_in[15];
    const float* ln2_b = (const float*)d_in[16];
    float* out = (float*)d_out;

    cudaFuncSetAttribute(k_qkv,    cudaFuncAttributeMaxDynamicSharedMemorySize, QKV_SMEM);
    cudaFuncSetAttribute(k_block2, cudaFuncAttributeMaxDynamicSharedMemorySize, FB_SMEM);

    k_cvt_w<<<64, 512>>>(Wq, Wk, Wv, Wo, W1, W2);
    k_qkv<<<dim3(M_TILES, 3), 256, QKV_SMEM>>>(x, bq, bk, bv);
    attn_kernel<<<NB * H_HEADS * TT, 256>>>();
    k_block2<<<M_TILES, 256, FB_SMEM>>>(x, bo, ln1_g, ln1_b, b1, b2, ln2_g, ln2_b, out);
}